// round 4
// baseline (speedup 1.0000x reference)
#include <cuda_runtime.h>
#include <math.h>

#define D_MODEL 768
#define D_INNER 1536
#define D_STATE 16
#define DT_RANK 96
#define SEQ     2048
#define BATCH   2
#define MTOT    (BATCH * SEQ)   // 4096
#define XDBL_W  128             // DT_RANK + 2*D_STATE

// ---------------- scratch (device globals: allocation-free) ----------------
__device__ float g_xn   [MTOT * D_MODEL];   // layernorm output
__device__ float g_u    [MTOT * D_INNER];   // pre-conv u
__device__ float g_v    [MTOT * D_INNER];   // gate branch
__device__ float g_uc   [MTOT * D_INNER];   // post conv+silu u
__device__ float g_xdbl [MTOT * XDBL_W];    // [dlt | B | C]
__device__ float g_delta[MTOT * D_INNER];   // softplus(dlt@W_dt + b_dt)
__device__ float g_y    [MTOT * D_INNER];   // scan out, gated

__device__ __forceinline__ float siluf(float x) {
    return x / (1.f + __expf(-x));
}

// ---------------- LayerNorm ----------------
__global__ __launch_bounds__(256) void ln_kernel(
    const float* __restrict__ x, const float* __restrict__ g,
    const float* __restrict__ b)
{
    int row = blockIdx.x;
    int tid = threadIdx.x;
    const float* xr = x + (size_t)row * D_MODEL;
    float v0 = xr[tid], v1 = xr[tid + 256], v2 = xr[tid + 512];
    float s  = v0 + v1 + v2;
    float sq = v0 * v0 + v1 * v1 + v2 * v2;
    #pragma unroll
    for (int o = 16; o > 0; o >>= 1) {
        s  += __shfl_xor_sync(0xffffffffu, s,  o);
        sq += __shfl_xor_sync(0xffffffffu, sq, o);
    }
    __shared__ float ss[8], ssq[8];
    __shared__ float s_mu, s_rstd;
    if ((tid & 31) == 0) { ss[tid >> 5] = s; ssq[tid >> 5] = sq; }
    __syncthreads();
    if (tid == 0) {
        float ts = 0.f, tq = 0.f;
        #pragma unroll
        for (int i = 0; i < 8; i++) { ts += ss[i]; tq += ssq[i]; }
        float mu  = ts / D_MODEL;
        float var = tq / D_MODEL - mu * mu;
        s_mu = mu;
        s_rstd = rsqrtf(var + 1e-5f);
    }
    __syncthreads();
    float mu = s_mu, rstd = s_rstd;
    float* o = g_xn + (size_t)row * D_MODEL;
    o[tid      ] = (v0 - mu) * rstd * g[tid      ] + b[tid      ];
    o[tid + 256] = (v1 - mu) * rstd * g[tid + 256] + b[tid + 256];
    o[tid + 512] = (v2 - mu) * rstd * g[tid + 512] + b[tid + 512];
}

// ---------------- generic tiled SGEMM, C = A@B (+epilogue) ----------------
// EPI 0: plain store
// EPI 1: split u/v (GEMM1): col<D_INNER -> C (stride D_INNER), else C2
// EPI 2: softplus(acc + extra[n]) (GEMM3)
// EPI 3: acc + extra[m*ldc+n] (residual add, GEMM_out)
template<int BM, int BN, int BK, int TM, int TN, int EPI>
__global__ __launch_bounds__(256) void sgemm_kernel(
    const float* __restrict__ A, int lda,
    const float* __restrict__ Bg, int ldb,
    float* __restrict__ C, int ldc, int K,
    const float* __restrict__ extra, float* __restrict__ C2)
{
    __shared__ float As[BK][BM + 4];
    __shared__ float Bs[BK][BN];

    const int tid = threadIdx.x;
    const int TX  = BN / TN;
    const int tx  = tid % TX;
    const int ty  = tid / TX;
    const int m0  = blockIdx.y * BM;
    const int n0  = blockIdx.x * BN;
    const int row0 = ty * TM;
    const int col0 = tx * TN;

    float acc[TM][TN];
    #pragma unroll
    for (int i = 0; i < TM; i++)
        #pragma unroll
        for (int j = 0; j < TN; j++) acc[i][j] = 0.f;

    for (int k0 = 0; k0 < K; k0 += BK) {
        #pragma unroll
        for (int i = tid; i < BM * BK; i += 256) {
            int r = i / BK, c = i % BK;
            As[c][r] = A[(size_t)(m0 + r) * lda + k0 + c];
        }
        #pragma unroll
        for (int i = tid; i < BK * BN; i += 256) {
            int r = i / BN, c = i % BN;
            Bs[r][c] = Bg[(size_t)(k0 + r) * ldb + n0 + c];
        }
        __syncthreads();
        #pragma unroll
        for (int k = 0; k < BK; k++) {
            float af[TM], bf[TN];
            #pragma unroll
            for (int i = 0; i < TM; i++) af[i] = As[k][row0 + i];
            #pragma unroll
            for (int j = 0; j < TN; j++) bf[j] = Bs[k][col0 + j];
            #pragma unroll
            for (int i = 0; i < TM; i++)
                #pragma unroll
                for (int j = 0; j < TN; j++)
                    acc[i][j] = fmaf(af[i], bf[j], acc[i][j]);
        }
        __syncthreads();
    }

    #pragma unroll
    for (int i = 0; i < TM; i++) {
        int gm = m0 + row0 + i;
        #pragma unroll
        for (int j = 0; j < TN; j++) {
            int gn = n0 + col0 + j;
            float val = acc[i][j];
            if (EPI == 0) {
                C[(size_t)gm * ldc + gn] = val;
            } else if (EPI == 1) {
                if (gn < D_INNER) C [(size_t)gm * D_INNER + gn]           = val;
                else              C2[(size_t)gm * D_INNER + gn - D_INNER] = val;
            } else if (EPI == 2) {
                float t = val + extra[gn];
                C[(size_t)gm * ldc + gn] = (t > 20.f) ? t : log1pf(__expf(t));
            } else {
                C[(size_t)gm * ldc + gn] = val + extra[(size_t)gm * ldc + gn];
            }
        }
    }
}

// ---------------- causal depthwise conv (k=4) + bias + silu ----------------
__global__ __launch_bounds__(256) void conv_silu_kernel(
    const float* __restrict__ cw, const float* __restrict__ cb)
{
    int idx = blockIdx.x * 256 + threadIdx.x;
    if (idx >= MTOT * D_INNER) return;
    int d = idx % D_INNER;
    int m = idx / D_INNER;
    int l = m & (SEQ - 1);
    float acc = cb[d];
    #pragma unroll
    for (int j = 0; j < 4; j++) {
        int li = l + j - 3;
        if (li >= 0)
            acc = fmaf(cw[d * 4 + j], g_u[(size_t)(m + j - 3) * D_INNER + d], acc);
    }
    g_uc[idx] = siluf(acc);
}

// ---------------- selective scan (fused + gate) ----------------
// 128 threads = 8 d-channels x 16 states. grid (D_INNER/8, BATCH).
__global__ __launch_bounds__(128) void scan_kernel(
    const float* __restrict__ logA, const float* __restrict__ Dp)
{
    int tid = threadIdx.x;
    int n  = tid & 15;
    int dl = tid >> 4;
    int d  = blockIdx.x * 8 + dl;
    int b  = blockIdx.y;

    float Adn = -expf(logA[d * D_STATE + n]);
    float Dd  = Dp[d];
    float h   = 0.f;
    int base  = b * SEQ;

    for (int l = 0; l < SEQ; l++) {
        int m = base + l;
        float dlt = g_delta[(size_t)m * D_INNER + d];
        float uu  = g_uc   [(size_t)m * D_INNER + d];
        float Bn  = g_xdbl [(size_t)m * XDBL_W + DT_RANK + n];
        float Cn  = g_xdbl [(size_t)m * XDBL_W + DT_RANK + D_STATE + n];
        h = fmaf(__expf(dlt * Adn), h, dlt * Bn * uu);
        float p = h * Cn;
        p += __shfl_xor_sync(0xffffffffu, p, 8, 16);
        p += __shfl_xor_sync(0xffffffffu, p, 4, 16);
        p += __shfl_xor_sync(0xffffffffu, p, 2, 16);
        p += __shfl_xor_sync(0xffffffffu, p, 1, 16);
        if (n == 0) {
            float vv = g_v[(size_t)m * D_INNER + d];
            g_y[(size_t)m * D_INNER + d] = (p + uu * Dd) * siluf(vv);
        }
    }
}

// ---------------- launch ----------------
extern "C" void kernel_launch(void* const* d_in, const int* in_sizes, int n_in,
                              void* d_out, int out_size)
{
    const float* x      = (const float*)d_in[0];
    const float* ln_g   = (const float*)d_in[1];
    const float* ln_b   = (const float*)d_in[2];
    const float* W_in   = (const float*)d_in[3];
    const float* conv_w = (const float*)d_in[4];
    const float* conv_b = (const float*)d_in[5];
    const float* W_xprj = (const float*)d_in[6];
    const float* W_dt   = (const float*)d_in[7];
    const float* b_dt   = (const float*)d_in[8];
    const float* log_A  = (const float*)d_in[9];
    const float* D_par  = (const float*)d_in[10];
    const float* W_out  = (const float*)d_in[11];
    float* out = (float*)d_out;

    float *p_xn, *p_u, *p_v, *p_uc, *p_xdbl, *p_delta, *p_y;
    cudaGetSymbolAddress((void**)&p_xn,    g_xn);
    cudaGetSymbolAddress((void**)&p_u,     g_u);
    cudaGetSymbolAddress((void**)&p_v,     g_v);
    cudaGetSymbolAddress((void**)&p_uc,    g_uc);
    cudaGetSymbolAddress((void**)&p_xdbl,  g_xdbl);
    cudaGetSymbolAddress((void**)&p_delta, g_delta);
    cudaGetSymbolAddress((void**)&p_y,     g_y);

    // 1. LayerNorm
    ln_kernel<<<MTOT, 256>>>(x, ln_g, ln_b);

    // 2. GEMM1: uv = xn @ W_in  (4096 x 3072 x 768), split u/v
    {
        dim3 grid(2 * D_INNER / 128, MTOT / 128);
        sgemm_kernel<128,128,16,8,8,1><<<grid, 256>>>(
            p_xn, D_MODEL, W_in, 2 * D_INNER, p_u, D_INNER, D_MODEL,
            nullptr, p_v);
    }

    // 3. depthwise causal conv + silu
    conv_silu_kernel<<<(MTOT * D_INNER + 255) / 256, 256>>>(conv_w, conv_b);

    // 4. GEMM2: x_dbl = uc @ W_xproj  (4096 x 128 x 1536)
    {
        dim3 grid(XDBL_W / 64, MTOT / 64);
        sgemm_kernel<64,64,16,4,4,0><<<grid, 256>>>(
            p_uc, D_INNER, W_xprj, XDBL_W, p_xdbl, XDBL_W, D_INNER,
            nullptr, nullptr);
    }

    // 5. GEMM3: delta = softplus(x_dbl[:, :96] @ W_dt + b_dt)  (4096 x 1536 x 96)
    {
        dim3 grid(D_INNER / 128, MTOT / 128);
        sgemm_kernel<128,128,16,8,8,2><<<grid, 256>>>(
            p_xdbl, XDBL_W, W_dt, D_INNER, p_delta, D_INNER, DT_RANK,
            b_dt, nullptr);
    }

    // 6. fused selective scan + skip + gate
    {
        dim3 grid(D_INNER / 8, BATCH);
        scan_kernel<<<grid, 128>>>(log_A, D_par);
    }

    // 7. GEMM_out: out = y_gated @ W_out + x  (4096 x 768 x 1536)
    {
        dim3 grid(D_MODEL / 64, MTOT / 128);
        sgemm_kernel<128,64,16,8,4,3><<<grid, 256>>>(
            p_y, D_INNER, W_out, D_MODEL, out, D_MODEL, D_INNER,
            x, nullptr);
    }
}

// round 5
// speedup vs baseline: 1.2869x; 1.2869x over previous
#include <cuda_runtime.h>
#include <math.h>

#define D_MODEL 768
#define D_INNER 1536
#define D_STATE 16
#define DT_RANK 96
#define SEQ     2048
#define BATCH   2
#define MTOT    (BATCH * SEQ)   // 4096
#define XDBL_W  128             // DT_RANK + 2*D_STATE

// ---------------- scratch (device globals: allocation-free) ----------------
__device__ float g_xn   [MTOT * D_MODEL];
__device__ float g_u    [MTOT * D_INNER];
__device__ float g_v    [MTOT * D_INNER];
__device__ float g_uc   [MTOT * D_INNER];
__device__ float g_xdbl [MTOT * XDBL_W];
__device__ float g_delta[MTOT * D_INNER];
__device__ float g_y    [MTOT * D_INNER];

__device__ __forceinline__ float siluf(float x) {
    return x / (1.f + __expf(-x));
}

__device__ __forceinline__ unsigned f2tf32(float f) {
    unsigned u;
    asm("cvt.rna.tf32.f32 %0, %1;" : "=r"(u) : "f"(f));
    return u;
}

// ---------------- LayerNorm ----------------
__global__ __launch_bounds__(256) void ln_kernel(
    const float* __restrict__ x, const float* __restrict__ g,
    const float* __restrict__ b)
{
    int row = blockIdx.x;
    int tid = threadIdx.x;
    const float* xr = x + (size_t)row * D_MODEL;
    float v0 = xr[tid], v1 = xr[tid + 256], v2 = xr[tid + 512];
    float s  = v0 + v1 + v2;
    float sq = v0 * v0 + v1 * v1 + v2 * v2;
    #pragma unroll
    for (int o = 16; o > 0; o >>= 1) {
        s  += __shfl_xor_sync(0xffffffffu, s,  o);
        sq += __shfl_xor_sync(0xffffffffu, sq, o);
    }
    __shared__ float ss[8], ssq[8];
    __shared__ float s_mu, s_rstd;
    if ((tid & 31) == 0) { ss[tid >> 5] = s; ssq[tid >> 5] = sq; }
    __syncthreads();
    if (tid == 0) {
        float ts = 0.f, tq = 0.f;
        #pragma unroll
        for (int i = 0; i < 8; i++) { ts += ss[i]; tq += ssq[i]; }
        float mu  = ts / D_MODEL;
        float var = tq / D_MODEL - mu * mu;
        s_mu = mu;
        s_rstd = rsqrtf(var + 1e-5f);
    }
    __syncthreads();
    float mu = s_mu, rstd = s_rstd;
    float* o = g_xn + (size_t)row * D_MODEL;
    o[tid      ] = (v0 - mu) * rstd * g[tid      ] + b[tid      ];
    o[tid + 256] = (v1 - mu) * rstd * g[tid + 256] + b[tid + 256];
    o[tid + 512] = (v2 - mu) * rstd * g[tid + 512] + b[tid + 512];
}

// ---------------- tf32 tensor-core GEMM ----------------
// C[M,N] = A[M,K] @ B[K,N], tf32 inputs (rna-rounded), fp32 accumulate.
// BM=128 fixed. 256 threads = 8 warps as 4(M) x 2(N).
// EPI 0: plain store
// EPI 1: split u/v: gn < D_INNER -> C, else C2 (both stride D_INNER)
// EPI 2: softplus(acc + extra[gn])
// EPI 3: acc + extra[gm*ldc+gn] (residual)
template<int BN, int EPI>
__global__ __launch_bounds__(256) void tf32_gemm(
    const float* __restrict__ A, int lda,
    const float* __restrict__ Bg, int ldb,
    float* __restrict__ C, int ldc, int K,
    const float* __restrict__ extra, float* __restrict__ C2)
{
    constexpr int BM = 128;
    constexpr int BK = 32;
    constexpr int WM = BM / 4;        // 32
    constexpr int WN = BN / 2;        // 64 or 32
    constexpr int MT = WM / 16;       // 2
    constexpr int NT = WN / 8;        // 8 or 4

    __shared__ unsigned As[BM][BK + 4];       // row-major, pad 4
    __shared__ unsigned Bs[BK][BN + 4];       // row k, col n, pad 4

    const int tid   = threadIdx.x;
    const int lane  = tid & 31;
    const int wid   = tid >> 5;
    const int warpM = wid & 3;
    const int warpN = wid >> 2;
    const int g     = lane >> 2;     // group id (0..7)
    const int t4    = lane & 3;      // thread in group

    const int m0 = blockIdx.y * BM;
    const int n0 = blockIdx.x * BN;
    const int wm0 = warpM * WM;
    const int wn0 = warpN * WN;

    float acc[MT][NT][4];
    #pragma unroll
    for (int i = 0; i < MT; i++)
        #pragma unroll
        for (int j = 0; j < NT; j++)
            #pragma unroll
            for (int c = 0; c < 4; c++) acc[i][j][c] = 0.f;

    // A fill mapping: 4096 words, 4 float4/thread
    const int ar = tid >> 3;           // 0..31, +32 per pass
    const int ac = (tid & 7) * 4;      // 0..28
    // B fill mapping: BN*32 words
    constexpr int BF = BN / 4;               // float4 per row
    constexpr int BROWS = 256 / BF;          // rows per pass
    constexpr int BPASS = BK / BROWS;        // passes
    const int br = tid / BF;
    const int bc = (tid % BF) * 4;

    for (int k0 = 0; k0 < K; k0 += BK) {
        #pragma unroll
        for (int i = 0; i < 4; i++) {
            int r = ar + i * 32;
            const float4 va = *(const float4*)&A[(size_t)(m0 + r) * lda + k0 + ac];
            As[r][ac    ] = f2tf32(va.x);
            As[r][ac + 1] = f2tf32(va.y);
            As[r][ac + 2] = f2tf32(va.z);
            As[r][ac + 3] = f2tf32(va.w);
        }
        #pragma unroll
        for (int i = 0; i < BPASS; i++) {
            int r = br + i * BROWS;
            const float4 vb = *(const float4*)&Bg[(size_t)(k0 + r) * ldb + n0 + bc];
            Bs[r][bc    ] = f2tf32(vb.x);
            Bs[r][bc + 1] = f2tf32(vb.y);
            Bs[r][bc + 2] = f2tf32(vb.z);
            Bs[r][bc + 3] = f2tf32(vb.w);
        }
        __syncthreads();

        #pragma unroll
        for (int kk = 0; kk < BK; kk += 8) {
            unsigned af[MT][4], bf[NT][2];
            #pragma unroll
            for (int mt = 0; mt < MT; mt++) {
                int mr = wm0 + mt * 16;
                af[mt][0] = As[mr + g    ][kk + t4    ];
                af[mt][1] = As[mr + g + 8][kk + t4    ];
                af[mt][2] = As[mr + g    ][kk + t4 + 4];
                af[mt][3] = As[mr + g + 8][kk + t4 + 4];
            }
            #pragma unroll
            for (int nt = 0; nt < NT; nt++) {
                int nc = wn0 + nt * 8 + g;
                bf[nt][0] = Bs[kk + t4    ][nc];
                bf[nt][1] = Bs[kk + t4 + 4][nc];
            }
            #pragma unroll
            for (int mt = 0; mt < MT; mt++)
                #pragma unroll
                for (int nt = 0; nt < NT; nt++) {
                    asm volatile(
                        "mma.sync.aligned.m16n8k8.row.col.f32.tf32.tf32.f32 "
                        "{%0,%1,%2,%3},{%4,%5,%6,%7},{%8,%9},{%0,%1,%2,%3};\n"
                        : "+f"(acc[mt][nt][0]), "+f"(acc[mt][nt][1]),
                          "+f"(acc[mt][nt][2]), "+f"(acc[mt][nt][3])
                        : "r"(af[mt][0]), "r"(af[mt][1]),
                          "r"(af[mt][2]), "r"(af[mt][3]),
                          "r"(bf[nt][0]), "r"(bf[nt][1]));
                }
        }
        __syncthreads();
    }

    // ---------------- epilogue ----------------
    #pragma unroll
    for (int mt = 0; mt < MT; mt++) {
        #pragma unroll
        for (int nt = 0; nt < NT; nt++) {
            int gm = m0 + wm0 + mt * 16 + g;
            int gn = n0 + wn0 + nt * 8 + 2 * t4;
            #pragma unroll
            for (int half = 0; half < 2; half++) {
                int row = gm + half * 8;
                float v0 = acc[mt][nt][half * 2];
                float v1 = acc[mt][nt][half * 2 + 1];
                if (EPI == 0) {
                    *(float2*)&C[(size_t)row * ldc + gn] = make_float2(v0, v1);
                } else if (EPI == 1) {
                    if (gn < D_INNER)
                        *(float2*)&C [(size_t)row * D_INNER + gn] = make_float2(v0, v1);
                    else
                        *(float2*)&C2[(size_t)row * D_INNER + gn - D_INNER] = make_float2(v0, v1);
                } else if (EPI == 2) {
                    float t0 = v0 + extra[gn];
                    float t1 = v1 + extra[gn + 1];
                    t0 = (t0 > 20.f) ? t0 : log1pf(__expf(t0));
                    t1 = (t1 > 20.f) ? t1 : log1pf(__expf(t1));
                    *(float2*)&C[(size_t)row * ldc + gn] = make_float2(t0, t1);
                } else {
                    float2 r = *(const float2*)&extra[(size_t)row * ldc + gn];
                    *(float2*)&C[(size_t)row * ldc + gn] =
                        make_float2(v0 + r.x, v1 + r.y);
                }
            }
        }
    }
}

// ---------------- causal depthwise conv (k=4) + bias + silu ----------------
__global__ __launch_bounds__(256) void conv_silu_kernel(
    const float* __restrict__ cw, const float* __restrict__ cb)
{
    int idx = blockIdx.x * 256 + threadIdx.x;
    if (idx >= MTOT * D_INNER) return;
    int d = idx % D_INNER;
    int m = idx / D_INNER;
    int l = m & (SEQ - 1);
    float acc = cb[d];
    #pragma unroll
    for (int j = 0; j < 4; j++) {
        int li = l + j - 3;
        if (li >= 0)
            acc = fmaf(cw[d * 4 + j], g_u[(size_t)(m + j - 3) * D_INNER + d], acc);
    }
    g_uc[idx] = siluf(acc);
}

// ---------------- selective scan (fused + gate) ----------------
__global__ __launch_bounds__(128) void scan_kernel(
    const float* __restrict__ logA, const float* __restrict__ Dp)
{
    int tid = threadIdx.x;
    int n  = tid & 15;
    int dl = tid >> 4;
    int d  = blockIdx.x * 8 + dl;
    int b  = blockIdx.y;

    float Adn = -expf(logA[d * D_STATE + n]);
    float Dd  = Dp[d];
    float h   = 0.f;
    int base  = b * SEQ;

    for (int l = 0; l < SEQ; l++) {
        int m = base + l;
        float dlt = g_delta[(size_t)m * D_INNER + d];
        float uu  = g_uc   [(size_t)m * D_INNER + d];
        float Bn  = g_xdbl [(size_t)m * XDBL_W + DT_RANK + n];
        float Cn  = g_xdbl [(size_t)m * XDBL_W + DT_RANK + D_STATE + n];
        h = fmaf(__expf(dlt * Adn), h, dlt * Bn * uu);
        float p = h * Cn;
        p += __shfl_xor_sync(0xffffffffu, p, 8, 16);
        p += __shfl_xor_sync(0xffffffffu, p, 4, 16);
        p += __shfl_xor_sync(0xffffffffu, p, 2, 16);
        p += __shfl_xor_sync(0xffffffffu, p, 1, 16);
        if (n == 0) {
            float vv = g_v[(size_t)m * D_INNER + d];
            g_y[(size_t)m * D_INNER + d] = (p + uu * Dd) * siluf(vv);
        }
    }
}

// ---------------- launch ----------------
extern "C" void kernel_launch(void* const* d_in, const int* in_sizes, int n_in,
                              void* d_out, int out_size)
{
    const float* x      = (const float*)d_in[0];
    const float* ln_g   = (const float*)d_in[1];
    const float* ln_b   = (const float*)d_in[2];
    const float* W_in   = (const float*)d_in[3];
    const float* conv_w = (const float*)d_in[4];
    const float* conv_b = (const float*)d_in[5];
    const float* W_xprj = (const float*)d_in[6];
    const float* W_dt   = (const float*)d_in[7];
    const float* b_dt   = (const float*)d_in[8];
    const float* log_A  = (const float*)d_in[9];
    const float* D_par  = (const float*)d_in[10];
    const float* W_out  = (const float*)d_in[11];
    float* out = (float*)d_out;

    float *p_xn, *p_u, *p_v, *p_uc, *p_xdbl, *p_delta, *p_y;
    cudaGetSymbolAddress((void**)&p_xn,    g_xn);
    cudaGetSymbolAddress((void**)&p_u,     g_u);
    cudaGetSymbolAddress((void**)&p_v,     g_v);
    cudaGetSymbolAddress((void**)&p_uc,    g_uc);
    cudaGetSymbolAddress((void**)&p_xdbl,  g_xdbl);
    cudaGetSymbolAddress((void**)&p_delta, g_delta);
    cudaGetSymbolAddress((void**)&p_y,     g_y);

    // 1. LayerNorm
    ln_kernel<<<MTOT, 256>>>(x, ln_g, ln_b);

    // 2. GEMM1: uv = xn @ W_in  (4096 x 3072 x 768), split u/v
    tf32_gemm<128, 1><<<dim3(2 * D_INNER / 128, MTOT / 128), 256>>>(
        p_xn, D_MODEL, W_in, 2 * D_INNER, p_u, D_INNER, D_MODEL, nullptr, p_v);

    // 3. depthwise causal conv + silu
    conv_silu_kernel<<<(MTOT * D_INNER + 255) / 256, 256>>>(conv_w, conv_b);

    // 4. GEMM2: x_dbl = uc @ W_xproj  (4096 x 128 x 1536)
    tf32_gemm<64, 0><<<dim3(XDBL_W / 64, MTOT / 128), 256>>>(
        p_uc, D_INNER, W_xprj, XDBL_W, p_xdbl, XDBL_W, D_INNER, nullptr, nullptr);

    // 5. GEMM3: delta = softplus(x_dbl[:, :96] @ W_dt + b_dt)  (4096 x 1536 x 96)
    tf32_gemm<128, 2><<<dim3(D_INNER / 128, MTOT / 128), 256>>>(
        p_xdbl, XDBL_W, W_dt, D_INNER, p_delta, D_INNER, DT_RANK, b_dt, nullptr);

    // 6. fused selective scan + skip + gate
    scan_kernel<<<dim3(D_INNER / 8, BATCH), 128>>>(log_A, D_par);

    // 7. GEMM_out: out = y_gated @ W_out + x  (4096 x 768 x 1536)
    tf32_gemm<128, 3><<<dim3(D_MODEL / 128, MTOT / 128), 256>>>(
        p_y, D_INNER, W_out, D_MODEL, out, D_MODEL, D_INNER, x, nullptr);
}

// round 7
// speedup vs baseline: 2.2793x; 1.7711x over previous
#include <cuda_runtime.h>
#include <math.h>

#define D_MODEL 768
#define D_INNER 1536
#define D_STATE 16
#define DT_RANK 96
#define SEQ     2048
#define BATCH   2
#define MTOT    (BATCH * SEQ)   // 4096
#define XDBL_W  128             // DT_RANK + 2*D_STATE

// ---------------- scratch (device globals: allocation-free) ----------------
__device__ float g_xn   [MTOT * D_MODEL];
__device__ float g_u    [MTOT * D_INNER];
__device__ float g_v    [MTOT * D_INNER];
__device__ float g_uc   [MTOT * D_INNER];
__device__ float g_xdbl [MTOT * XDBL_W];
__device__ float g_delta[MTOT * D_INNER];
__device__ float g_y    [MTOT * D_INNER];

__device__ __forceinline__ float siluf(float x) {
    return x / (1.f + __expf(-x));
}

__device__ __forceinline__ unsigned f2tf32(float f) {
    unsigned u;
    asm("cvt.rna.tf32.f32 %0, %1;" : "=r"(u) : "f"(f));
    return u;
}

// ---------------- LayerNorm ----------------
__global__ __launch_bounds__(256) void ln_kernel(
    const float* __restrict__ x, const float* __restrict__ g,
    const float* __restrict__ b)
{
    int row = blockIdx.x;
    int tid = threadIdx.x;
    const float* xr = x + (size_t)row * D_MODEL;
    float v0 = xr[tid], v1 = xr[tid + 256], v2 = xr[tid + 512];
    float s  = v0 + v1 + v2;
    float sq = v0 * v0 + v1 * v1 + v2 * v2;
    #pragma unroll
    for (int o = 16; o > 0; o >>= 1) {
        s  += __shfl_xor_sync(0xffffffffu, s,  o);
        sq += __shfl_xor_sync(0xffffffffu, sq, o);
    }
    __shared__ float ss[8], ssq[8];
    __shared__ float s_mu, s_rstd;
    if ((tid & 31) == 0) { ss[tid >> 5] = s; ssq[tid >> 5] = sq; }
    __syncthreads();
    if (tid == 0) {
        float ts = 0.f, tq = 0.f;
        #pragma unroll
        for (int i = 0; i < 8; i++) { ts += ss[i]; tq += ssq[i]; }
        float mu  = ts / D_MODEL;
        float var = tq / D_MODEL - mu * mu;
        s_mu = mu;
        s_rstd = rsqrtf(var + 1e-5f);
    }
    __syncthreads();
    float mu = s_mu, rstd = s_rstd;
    float* o = g_xn + (size_t)row * D_MODEL;
    o[tid      ] = (v0 - mu) * rstd * g[tid      ] + b[tid      ];
    o[tid + 256] = (v1 - mu) * rstd * g[tid + 256] + b[tid + 256];
    o[tid + 512] = (v2 - mu) * rstd * g[tid + 512] + b[tid + 512];
}

// ---------------- pipelined tf32 tensor-core GEMM ----------------
// C[M,N] = A[M,K] @ B[K,N], rna-rounded tf32 inputs, fp32 accumulate.
// 256 threads = 8 warps laid out WARPS_M x (8/WARPS_M).
// Double-buffered SMEM + register prefetch: one __syncthreads per BK step.
// EPI 0: plain store
// EPI 1: split u/v: gn < D_INNER -> C, else C2 (both stride D_INNER)
// EPI 2: softplus(acc + extra[gn])
// EPI 3: acc + extra[gm*ldc+gn] (residual)
template<int BM, int BN, int WARPS_M, int EPI>
__global__ __launch_bounds__(256) void tf32_gemm(
    const float* __restrict__ A, int lda,
    const float* __restrict__ Bg, int ldb,
    float* __restrict__ C, int ldc, int K,
    const float* __restrict__ extra, float* __restrict__ C2)
{
    constexpr int BK = 32;
    constexpr int WARPS_N = 8 / WARPS_M;
    constexpr int WM = BM / WARPS_M;
    constexpr int WN = BN / WARPS_N;
    constexpr int MT = WM / 16;
    constexpr int NT = WN / 8;
    constexpr int ASTR = BK + 4;          // A row stride (words)
    constexpr int BSTR = BN + 8;          // B row stride: bank-stride 8 -> conflict-free frags
    constexpr int APASS = BM / 32;        // float4 A loads per thread
    constexpr int BF    = BN / 4;         // float4 per B row
    constexpr int BR    = 256 / BF;       // B rows per pass
    constexpr int BPASS = BK / BR;        // float4 B loads per thread

    extern __shared__ unsigned sh[];
    unsigned* AsB = sh;                       // [2][BM][ASTR]
    unsigned* BsB = sh + 2 * BM * ASTR;       // [2][BK][BSTR]

    const int tid   = threadIdx.x;
    const int lane  = tid & 31;
    const int wid   = tid >> 5;
    const int warpM = wid % WARPS_M;
    const int warpN = wid / WARPS_M;
    const int g  = lane >> 2;
    const int t4 = lane & 3;

    const int m0  = blockIdx.y * BM;
    const int n0  = blockIdx.x * BN;
    const int wm0 = warpM * WM;
    const int wn0 = warpN * WN;

    const int ar = tid >> 3;           // A fill row (stride 32)
    const int ac = (tid & 7) * 4;      // A fill col
    const int br = tid / BF;           // B fill row (stride BR)
    const int bc = (tid % BF) * 4;     // B fill col

    float acc[MT][NT][4];
    #pragma unroll
    for (int i = 0; i < MT; i++)
        #pragma unroll
        for (int j = 0; j < NT; j++)
            #pragma unroll
            for (int c = 0; c < 4; c++) acc[i][j][c] = 0.f;

    float4 pA[APASS], pB[BPASS];

    auto load_tile = [&](int k0) {
        #pragma unroll
        for (int i = 0; i < APASS; i++)
            pA[i] = *(const float4*)&A[(size_t)(m0 + ar + i * 32) * lda + k0 + ac];
        #pragma unroll
        for (int i = 0; i < BPASS; i++)
            pB[i] = *(const float4*)&Bg[(size_t)(k0 + br + i * BR) * ldb + n0 + bc];
    };

    load_tile(0);
    int buf = 0;

    for (int k0 = 0; k0 < K; k0 += BK) {
        unsigned* As = AsB + buf * BM * ASTR;
        unsigned* Bs = BsB + buf * BK * BSTR;

        #pragma unroll
        for (int i = 0; i < APASS; i++) {
            unsigned* p = As + (ar + i * 32) * ASTR + ac;
            p[0] = f2tf32(pA[i].x); p[1] = f2tf32(pA[i].y);
            p[2] = f2tf32(pA[i].z); p[3] = f2tf32(pA[i].w);
        }
        #pragma unroll
        for (int i = 0; i < BPASS; i++) {
            unsigned* p = Bs + (br + i * BR) * BSTR + bc;
            p[0] = f2tf32(pB[i].x); p[1] = f2tf32(pB[i].y);
            p[2] = f2tf32(pB[i].z); p[3] = f2tf32(pB[i].w);
        }
        __syncthreads();

        if (k0 + BK < K) load_tile(k0 + BK);   // GMEM latency hidden by MMA below

        #pragma unroll
        for (int kk = 0; kk < BK; kk += 8) {
            unsigned af[MT][4], bf[NT][2];
            #pragma unroll
            for (int mt = 0; mt < MT; mt++) {
                const unsigned* a = As + (wm0 + mt * 16 + g) * ASTR + kk + t4;
                af[mt][0] = a[0];
                af[mt][1] = a[8 * ASTR];
                af[mt][2] = a[4];
                af[mt][3] = a[8 * ASTR + 4];
            }
            #pragma unroll
            for (int nt = 0; nt < NT; nt++) {
                const unsigned* b = Bs + (kk + t4) * BSTR + wn0 + nt * 8 + g;
                bf[nt][0] = b[0];
                bf[nt][1] = b[4 * BSTR];
            }
            #pragma unroll
            for (int mt = 0; mt < MT; mt++)
                #pragma unroll
                for (int nt = 0; nt < NT; nt++) {
                    asm volatile(
                        "mma.sync.aligned.m16n8k8.row.col.f32.tf32.tf32.f32 "
                        "{%0,%1,%2,%3},{%4,%5,%6,%7},{%8,%9},{%0,%1,%2,%3};\n"
                        : "+f"(acc[mt][nt][0]), "+f"(acc[mt][nt][1]),
                          "+f"(acc[mt][nt][2]), "+f"(acc[mt][nt][3])
                        : "r"(af[mt][0]), "r"(af[mt][1]),
                          "r"(af[mt][2]), "r"(af[mt][3]),
                          "r"(bf[nt][0]), "r"(bf[nt][1]));
                }
        }
        buf ^= 1;
    }

    // ---------------- epilogue ----------------
    #pragma unroll
    for (int mt = 0; mt < MT; mt++) {
        #pragma unroll
        for (int nt = 0; nt < NT; nt++) {
            int gm = m0 + wm0 + mt * 16 + g;
            int gn = n0 + wn0 + nt * 8 + 2 * t4;
            #pragma unroll
            for (int half = 0; half < 2; half++) {
                int row = gm + half * 8;
                float v0 = acc[mt][nt][half * 2];
                float v1 = acc[mt][nt][half * 2 + 1];
                if (EPI == 0) {
                    *(float2*)&C[(size_t)row * ldc + gn] = make_float2(v0, v1);
                } else if (EPI == 1) {
                    if (gn < D_INNER)
                        *(float2*)&C [(size_t)row * D_INNER + gn] = make_float2(v0, v1);
                    else
                        *(float2*)&C2[(size_t)row * D_INNER + gn - D_INNER] = make_float2(v0, v1);
                } else if (EPI == 2) {
                    float t0 = v0 + extra[gn];
                    float t1 = v1 + extra[gn + 1];
                    t0 = (t0 > 20.f) ? t0 : log1pf(__expf(t0));
                    t1 = (t1 > 20.f) ? t1 : log1pf(__expf(t1));
                    *(float2*)&C[(size_t)row * ldc + gn] = make_float2(t0, t1);
                } else {
                    float2 r = *(const float2*)&extra[(size_t)row * ldc + gn];
                    *(float2*)&C[(size_t)row * ldc + gn] =
                        make_float2(v0 + r.x, v1 + r.y);
                }
            }
        }
    }
}

// ---------------- causal depthwise conv (k=4) + bias + silu, float4 ----------------
__global__ __launch_bounds__(256) void conv_silu_kernel(
    const float* __restrict__ cw, const float* __restrict__ cb)
{
    int idx = blockIdx.x * 256 + threadIdx.x;       // over MTOT * D_INNER/4
    if (idx >= MTOT * (D_INNER / 4)) return;
    int d4 = idx % (D_INNER / 4);
    int m  = idx / (D_INNER / 4);
    int d  = d4 * 4;
    int l  = m & (SEQ - 1);

    float4 a = *(const float4*)&cb[d];
    #pragma unroll
    for (int j = 0; j < 4; j++) {
        int li = l + j - 3;
        if (li >= 0) {
            float4 uv = *(const float4*)&g_u[(size_t)(m + j - 3) * D_INNER + d];
            a.x = fmaf(cw[(d    ) * 4 + j], uv.x, a.x);
            a.y = fmaf(cw[(d + 1) * 4 + j], uv.y, a.y);
            a.z = fmaf(cw[(d + 2) * 4 + j], uv.z, a.z);
            a.w = fmaf(cw[(d + 3) * 4 + j], uv.w, a.w);
        }
    }
    a.x = siluf(a.x); a.y = siluf(a.y); a.z = siluf(a.z); a.w = siluf(a.w);
    *(float4*)&g_uc[(size_t)m * D_INNER + d] = a;
}

// ---------------- selective scan (fused + gate), software-pipelined ----------------
// 128 threads = 8 d-channels x 16 states. grid (D_INNER/8, BATCH).
__global__ __launch_bounds__(128) void scan_kernel(
    const float* __restrict__ logA, const float* __restrict__ Dp)
{
    int tid = threadIdx.x;
    int n  = tid & 15;
    int dl = tid >> 4;
    int d  = blockIdx.x * 8 + dl;
    int b  = blockIdx.y;

    float Adn = -expf(logA[d * D_STATE + n]);
    float Dd  = Dp[d];
    float h   = 0.f;

    size_t mi = (size_t)(b * SEQ) * D_INNER + d;
    size_t xi = (size_t)(b * SEQ) * XDBL_W + DT_RANK + n;

    // prefetch l = 0
    float dlt = g_delta[mi];
    float uu  = g_uc[mi];
    float Bn  = g_xdbl[xi];
    float Cn  = g_xdbl[xi + D_STATE];
    float vv  = g_v[mi];

    for (int l = 0; l < SEQ; l++) {
        float ndlt = 0.f, nuu = 0.f, nBn = 0.f, nCn = 0.f, nvv = 0.f;
        if (l + 1 < SEQ) {
            size_t mi2 = mi + D_INNER, xi2 = xi + XDBL_W;
            ndlt = g_delta[mi2];
            nuu  = g_uc[mi2];
            nBn  = g_xdbl[xi2];
            nCn  = g_xdbl[xi2 + D_STATE];
            nvv  = g_v[mi2];
        }
        float e = __expf(dlt * Adn);
        h = fmaf(e, h, dlt * Bn * uu);
        float p = h * Cn;
        p += __shfl_xor_sync(0xffffffffu, p, 8, 16);
        p += __shfl_xor_sync(0xffffffffu, p, 4, 16);
        p += __shfl_xor_sync(0xffffffffu, p, 2, 16);
        p += __shfl_xor_sync(0xffffffffu, p, 1, 16);
        if (n == 0)
            g_y[mi] = (p + uu * Dd) * siluf(vv);
        mi += D_INNER; xi += XDBL_W;
        dlt = ndlt; uu = nuu; Bn = nBn; Cn = nCn; vv = nvv;
    }
}

// ---------------- launch ----------------
extern "C" void kernel_launch(void* const* d_in, const int* in_sizes, int n_in,
                              void* d_out, int out_size)
{
    const float* x      = (const float*)d_in[0];
    const float* ln_g   = (const float*)d_in[1];
    const float* ln_b   = (const float*)d_in[2];
    const float* W_in   = (const float*)d_in[3];
    const float* conv_w = (const float*)d_in[4];
    const float* conv_b = (const float*)d_in[5];
    const float* W_xprj = (const float*)d_in[6];
    const float* W_dt   = (const float*)d_in[7];
    const float* b_dt   = (const float*)d_in[8];
    const float* log_A  = (const float*)d_in[9];
    const float* D_par  = (const float*)d_in[10];
    const float* W_out  = (const float*)d_in[11];
    float* out = (float*)d_out;

    float *p_xn, *p_u, *p_v, *p_uc, *p_xdbl, *p_delta, *p_y;
    cudaGetSymbolAddress((void**)&p_xn,    g_xn);
    cudaGetSymbolAddress((void**)&p_u,     g_u);
    cudaGetSymbolAddress((void**)&p_v,     g_v);
    cudaGetSymbolAddress((void**)&p_uc,    g_uc);
    cudaGetSymbolAddress((void**)&p_xdbl,  g_xdbl);
    cudaGetSymbolAddress((void**)&p_delta, g_delta);
    cudaGetSymbolAddress((void**)&p_y,     g_y);

    auto smem_sz = [](int BM, int BN) {
        return (size_t)(2 * BM * (32 + 4) + 2 * 32 * (BN + 8)) * 4;
    };
    const size_t sm_128_128 = smem_sz(128, 128);   // 71680
    const size_t sm_64_32   = smem_sz(64, 32);     // 28672
    const size_t sm_128_64  = smem_sz(128, 64);    // 55296

    cudaFuncSetAttribute((const void*)tf32_gemm<128, 128, 4, 1>,
                         cudaFuncAttributeMaxDynamicSharedMemorySize, (int)sm_128_128);
    cudaFuncSetAttribute((const void*)tf32_gemm<128, 128, 4, 2>,
                         cudaFuncAttributeMaxDynamicSharedMemorySize, (int)sm_128_128);
    cudaFuncSetAttribute((const void*)tf32_gemm<128, 64, 4, 3>,
                         cudaFuncAttributeMaxDynamicSharedMemorySize, (int)sm_128_64);

    // 1. LayerNorm
    ln_kernel<<<MTOT, 256>>>(x, ln_g, ln_b);

    // 2. GEMM1: uv = xn @ W_in  (4096 x 3072 x 768), split u/v
    tf32_gemm<128, 128, 4, 1><<<dim3(2 * D_INNER / 128, MTOT / 128), 256, sm_128_128>>>(
        p_xn, D_MODEL, W_in, 2 * D_INNER, p_u, D_INNER, D_MODEL, nullptr, p_v);

    // 3. depthwise causal conv + silu
    conv_silu_kernel<<<(MTOT * (D_INNER / 4) + 255) / 256, 256>>>(conv_w, conv_b);

    // 4. GEMM2: x_dbl = uc @ W_xproj  (4096 x 128 x 1536)  [64x32 tiles -> 256 CTAs]
    tf32_gemm<64, 32, 4, 0><<<dim3(XDBL_W / 32, MTOT / 64), 256, sm_64_32>>>(
        p_uc, D_INNER, W_xprj, XDBL_W, p_xdbl, XDBL_W, D_INNER, nullptr, nullptr);

    // 5. GEMM3: delta = softplus(x_dbl[:, :96] @ W_dt + b_dt)  (4096 x 1536 x 96)
    tf32_gemm<128, 128, 4, 2><<<dim3(D_INNER / 128, MTOT / 128), 256, sm_128_128>>>(
        p_xdbl, XDBL_W, W_dt, D_INNER, p_delta, D_INNER, DT_RANK, b_dt, nullptr);

    // 6. fused selective scan + skip + gate
    scan_kernel<<<dim3(D_INNER / 8, BATCH), 128>>>(log_A, D_par);

    // 7. GEMM_out: out = y_gated @ W_out + x  (4096 x 768 x 1536)  [128x64 -> 384 CTAs]
    tf32_gemm<128, 64, 4, 3><<<dim3(D_MODEL / 64, MTOT / 128), 256, sm_128_64>>>(
        p_y, D_INNER, W_out, D_MODEL, out, D_MODEL, D_INNER, x, nullptr);
}

// round 9
// speedup vs baseline: 2.3886x; 1.0480x over previous
#include <cuda_runtime.h>
#include <math.h>

#define D_MODEL 768
#define D_INNER 1536
#define D_STATE 16
#define DT_RANK 96
#define SEQ     2048
#define BATCH   2
#define MTOT    (BATCH * SEQ)   // 4096
#define XDBL_W  128             // DT_RANK + 2*D_STATE

// ---------------- scratch (device globals: allocation-free) ----------------
__device__ float g_xn   [MTOT * D_MODEL];
__device__ float g_u    [MTOT * D_INNER];
__device__ float g_v    [MTOT * D_INNER];
__device__ float g_uc   [MTOT * D_INNER];
__device__ float g_xdbl [MTOT * XDBL_W];
__device__ float g_delta[MTOT * D_INNER];
__device__ float g_y    [MTOT * D_INNER];

// converted (tf32-rounded) weights
#define WIN_SZ  (D_MODEL * 2 * D_INNER)        // 2359296
#define WXP_SZ  (D_INNER * XDBL_W)             // 196608
#define WDT_SZ  (DT_RANK * D_INNER)            // 147456
#define WOUT_SZ (D_INNER * D_MODEL)            // 1179648
#define WXP_OFF  (WIN_SZ)
#define WDT_OFF  (WIN_SZ + WXP_SZ)
#define WOUT_OFF (WIN_SZ + WXP_SZ + WDT_SZ)
__device__ float g_wc[WIN_SZ + WXP_SZ + WDT_SZ + WOUT_SZ];

__device__ __forceinline__ float siluf(float x) {
    return x / (1.f + __expf(-x));
}

__device__ __forceinline__ float rtf32(float f) {
    unsigned u;
    asm("cvt.rna.tf32.f32 %0, %1;" : "=r"(u) : "f"(f));
    return __uint_as_float(u);
}

__device__ __forceinline__ void cp_async16(unsigned saddr, const void* gptr) {
    asm volatile("cp.async.cg.shared.global [%0], [%1], 16;"
                 :: "r"(saddr), "l"(gptr));
}

// ---------------- weight conversion (fp32 -> rna tf32 bits) ----------------
__global__ __launch_bounds__(256) void cvt_weights_kernel(
    const float* __restrict__ Win, const float* __restrict__ Wxp,
    const float* __restrict__ Wdt, const float* __restrict__ Wout)
{
    int i4 = blockIdx.x * 256 + threadIdx.x;
    const int T4 = (WIN_SZ + WXP_SZ + WDT_SZ + WOUT_SZ) / 4;
    if (i4 >= T4) return;
    int i = i4 * 4;
    const float* src;
    int off;
    if (i < WXP_OFF)       { src = Win;  off = i; }
    else if (i < WDT_OFF)  { src = Wxp;  off = i - WXP_OFF; }
    else if (i < WOUT_OFF) { src = Wdt;  off = i - WDT_OFF; }
    else                   { src = Wout; off = i - WOUT_OFF; }
    float4 v = *(const float4*)&src[off];
    v.x = rtf32(v.x); v.y = rtf32(v.y); v.z = rtf32(v.z); v.w = rtf32(v.w);
    *(float4*)&g_wc[i] = v;
}

// ---------------- LayerNorm (writes tf32-rounded xn) ----------------
__global__ __launch_bounds__(256) void ln_kernel(
    const float* __restrict__ x, const float* __restrict__ g,
    const float* __restrict__ b)
{
    int row = blockIdx.x;
    int tid = threadIdx.x;
    const float* xr = x + (size_t)row * D_MODEL;
    float v0 = xr[tid], v1 = xr[tid + 256], v2 = xr[tid + 512];
    float s  = v0 + v1 + v2;
    float sq = v0 * v0 + v1 * v1 + v2 * v2;
    #pragma unroll
    for (int o = 16; o > 0; o >>= 1) {
        s  += __shfl_xor_sync(0xffffffffu, s,  o);
        sq += __shfl_xor_sync(0xffffffffu, sq, o);
    }
    __shared__ float ss[8], ssq[8];
    __shared__ float s_mu, s_rstd;
    if ((tid & 31) == 0) { ss[tid >> 5] = s; ssq[tid >> 5] = sq; }
    __syncthreads();
    if (tid == 0) {
        float ts = 0.f, tq = 0.f;
        #pragma unroll
        for (int i = 0; i < 8; i++) { ts += ss[i]; tq += ssq[i]; }
        float mu  = ts / D_MODEL;
        float var = tq / D_MODEL - mu * mu;
        s_mu = mu;
        s_rstd = rsqrtf(var + 1e-5f);
    }
    __syncthreads();
    float mu = s_mu, rstd = s_rstd;
    float* o = g_xn + (size_t)row * D_MODEL;
    o[tid      ] = rtf32((v0 - mu) * rstd * g[tid      ] + b[tid      ]);
    o[tid + 256] = rtf32((v1 - mu) * rstd * g[tid + 256] + b[tid + 256]);
    o[tid + 512] = rtf32((v2 - mu) * rstd * g[tid + 512] + b[tid + 512]);
}

// ---------------- cp.async 3-stage pipelined tf32 GEMM ----------------
// Operands must already be tf32-rounded. 256 threads = 8 warps (4x2).
// EPI 0: store tf32-rounded (feeds GEMM3 A + scan B/C)
// EPI 1: split u/v: gn < D_INNER -> C (fp32), else C2 (fp32)
// EPI 2: softplus(acc + extra[gn]) fp32
// EPI 3: acc + extra[gm*ldc+gn] fp32 (residual)
template<int BM, int BN, int EPI>
__global__ __launch_bounds__(256, 2) void tf32_gemm(
    const float* __restrict__ A, int lda,
    const float* __restrict__ Bg, int ldb,
    float* __restrict__ C, int ldc, int K,
    const float* __restrict__ extra, float* __restrict__ C2)
{
    constexpr int BK = 32;
    constexpr int STAGES = 3;
    constexpr int WARPS_M = 4, WARPS_N = 2;
    constexpr int WM = BM / WARPS_M, WN = BN / WARPS_N;
    constexpr int MT = WM / 16, NT = WN / 8;
    constexpr int ASTR = BK + 4;           // 36: frag banks 4g+t4, conflict-free
    constexpr int BSTR = BN + 8;           // frag banks 8t4+g, conflict-free
    constexpr int ATILE = BM * ASTR;
    constexpr int BTILE = BK * BSTR;
    constexpr int STAGE = ATILE + BTILE;
    constexpr int APASS = BM / 32;
    constexpr int BF4   = BN / 4;
    constexpr int BR    = 256 / BF4;
    constexpr int BPASS = BK / BR;

    extern __shared__ float sh[];
    const unsigned sbase = (unsigned)__cvta_generic_to_shared(sh);

    const int tid  = threadIdx.x;
    const int lane = tid & 31;
    const int wid  = tid >> 5;
    const int warpM = wid % WARPS_M;
    const int warpN = wid / WARPS_M;
    const int g  = lane >> 2;
    const int t4 = lane & 3;

    const int m0  = blockIdx.y * BM;
    const int n0  = blockIdx.x * BN;
    const int wm0 = warpM * WM;
    const int wn0 = warpN * WN;

    const int ar = tid >> 3;
    const int ac = (tid & 7) * 4;
    const int br = tid / BF4;
    const int bc = (tid % BF4) * 4;

    const int KT = K / BK;

    auto issue = [&](int s) {
        if (s < KT) {
            int k0 = s * BK;
            unsigned abase = sbase + (unsigned)((s % STAGES) * STAGE) * 4u;
            unsigned bbase = abase + (unsigned)ATILE * 4u;
            #pragma unroll
            for (int i = 0; i < APASS; i++)
                cp_async16(abase + ((ar + i * 32) * ASTR + ac) * 4,
                           &A[(size_t)(m0 + ar + i * 32) * lda + k0 + ac]);
            #pragma unroll
            for (int i = 0; i < BPASS; i++)
                cp_async16(bbase + ((br + i * BR) * BSTR + bc) * 4,
                           &Bg[(size_t)(k0 + br + i * BR) * ldb + n0 + bc]);
        }
        asm volatile("cp.async.commit_group;");
    };

    float acc[MT][NT][4];
    #pragma unroll
    for (int i = 0; i < MT; i++)
        #pragma unroll
        for (int j = 0; j < NT; j++)
            #pragma unroll
            for (int c = 0; c < 4; c++) acc[i][j][c] = 0.f;

    issue(0);
    issue(1);

    for (int it = 0; it < KT; it++) {
        asm volatile("cp.async.wait_group 1;");
        __syncthreads();
        issue(it + 2);   // overwrites buffer of iter it-1; safe past the sync

        const float* As = sh + (it % STAGES) * STAGE;
        const float* Bs = As + ATILE;

        #pragma unroll
        for (int kk = 0; kk < BK; kk += 8) {
            unsigned af[MT][4], bf[NT][2];
            #pragma unroll
            for (int mt = 0; mt < MT; mt++) {
                const float* a = As + (wm0 + mt * 16 + g) * ASTR + kk + t4;
                af[mt][0] = __float_as_uint(a[0]);
                af[mt][1] = __float_as_uint(a[8 * ASTR]);
                af[mt][2] = __float_as_uint(a[4]);
                af[mt][3] = __float_as_uint(a[8 * ASTR + 4]);
            }
            #pragma unroll
            for (int nt = 0; nt < NT; nt++) {
                const float* b = Bs + (kk + t4) * BSTR + wn0 + nt * 8 + g;
                bf[nt][0] = __float_as_uint(b[0]);
                bf[nt][1] = __float_as_uint(b[4 * BSTR]);
            }
            #pragma unroll
            for (int mt = 0; mt < MT; mt++)
                #pragma unroll
                for (int nt = 0; nt < NT; nt++) {
                    asm volatile(
                        "mma.sync.aligned.m16n8k8.row.col.f32.tf32.tf32.f32 "
                        "{%0,%1,%2,%3},{%4,%5,%6,%7},{%8,%9},{%0,%1,%2,%3};\n"
                        : "+f"(acc[mt][nt][0]), "+f"(acc[mt][nt][1]),
                          "+f"(acc[mt][nt][2]), "+f"(acc[mt][nt][3])
                        : "r"(af[mt][0]), "r"(af[mt][1]),
                          "r"(af[mt][2]), "r"(af[mt][3]),
                          "r"(bf[nt][0]), "r"(bf[nt][1]));
                }
        }
    }

    // ---------------- epilogue ----------------
    #pragma unroll
    for (int mt = 0; mt < MT; mt++) {
        #pragma unroll
        for (int nt = 0; nt < NT; nt++) {
            int gm = m0 + wm0 + mt * 16 + g;
            int gn = n0 + wn0 + nt * 8 + 2 * t4;
            #pragma unroll
            for (int half = 0; half < 2; half++) {
                int row = gm + half * 8;
                float v0 = acc[mt][nt][half * 2];
                float v1 = acc[mt][nt][half * 2 + 1];
                if (EPI == 0) {
                    *(float2*)&C[(size_t)row * ldc + gn] =
                        make_float2(rtf32(v0), rtf32(v1));
                } else if (EPI == 1) {
                    if (gn < D_INNER)
                        *(float2*)&C [(size_t)row * D_INNER + gn] = make_float2(v0, v1);
                    else
                        *(float2*)&C2[(size_t)row * D_INNER + gn - D_INNER] = make_float2(v0, v1);
                } else if (EPI == 2) {
                    float t0 = v0 + extra[gn];
                    float t1 = v1 + extra[gn + 1];
                    t0 = (t0 > 20.f) ? t0 : log1pf(__expf(t0));
                    t1 = (t1 > 20.f) ? t1 : log1pf(__expf(t1));
                    *(float2*)&C[(size_t)row * ldc + gn] = make_float2(t0, t1);
                } else {
                    float2 r = *(const float2*)&extra[(size_t)row * ldc + gn];
                    *(float2*)&C[(size_t)row * ldc + gn] =
                        make_float2(v0 + r.x, v1 + r.y);
                }
            }
        }
    }
}

// ---------------- causal depthwise conv (k=4) + bias + silu, float4 ----------------
// writes tf32-rounded uc (GEMM2 A operand; scan reads same values)
__global__ __launch_bounds__(256) void conv_silu_kernel(
    const float* __restrict__ cw, const float* __restrict__ cb)
{
    int idx = blockIdx.x * 256 + threadIdx.x;
    if (idx >= MTOT * (D_INNER / 4)) return;
    int d4 = idx % (D_INNER / 4);
    int m  = idx / (D_INNER / 4);
    int d  = d4 * 4;
    int l  = m & (SEQ - 1);

    float4 a = *(const float4*)&cb[d];
    #pragma unroll
    for (int j = 0; j < 4; j++) {
        int li = l + j - 3;
        if (li >= 0) {
            float4 uv = *(const float4*)&g_u[(size_t)(m + j - 3) * D_INNER + d];
            a.x = fmaf(cw[(d    ) * 4 + j], uv.x, a.x);
            a.y = fmaf(cw[(d + 1) * 4 + j], uv.y, a.y);
            a.z = fmaf(cw[(d + 2) * 4 + j], uv.z, a.z);
            a.w = fmaf(cw[(d + 3) * 4 + j], uv.w, a.w);
        }
    }
    a.x = rtf32(siluf(a.x)); a.y = rtf32(siluf(a.y));
    a.z = rtf32(siluf(a.z)); a.w = rtf32(siluf(a.w));
    *(float4*)&g_uc[(size_t)m * D_INNER + d] = a;
}

// ---------------- selective scan (fused + gate), software-pipelined ----------------
__global__ __launch_bounds__(128) void scan_kernel(
    const float* __restrict__ logA, const float* __restrict__ Dp)
{
    int tid = threadIdx.x;
    int n  = tid & 15;
    int dl = tid >> 4;
    int d  = blockIdx.x * 8 + dl;
    int b  = blockIdx.y;

    float Adn = -expf(logA[d * D_STATE + n]);
    float Dd  = Dp[d];
    float h   = 0.f;

    size_t mi = (size_t)(b * SEQ) * D_INNER + d;
    size_t xi = (size_t)(b * SEQ) * XDBL_W + DT_RANK + n;

    float dlt = g_delta[mi];
    float uu  = g_uc[mi];
    float Bn  = g_xdbl[xi];
    float Cn  = g_xdbl[xi + D_STATE];
    float vv  = g_v[mi];

    for (int l = 0; l < SEQ; l++) {
        float ndlt = 0.f, nuu = 0.f, nBn = 0.f, nCn = 0.f, nvv = 0.f;
        if (l + 1 < SEQ) {
            size_t mi2 = mi + D_INNER, xi2 = xi + XDBL_W;
            ndlt = g_delta[mi2];
            nuu  = g_uc[mi2];
            nBn  = g_xdbl[xi2];
            nCn  = g_xdbl[xi2 + D_STATE];
            nvv  = g_v[mi2];
        }
        float e = __expf(dlt * Adn);
        h = fmaf(e, h, dlt * Bn * uu);
        float p = h * Cn;
        p += __shfl_xor_sync(0xffffffffu, p, 8, 16);
        p += __shfl_xor_sync(0xffffffffu, p, 4, 16);
        p += __shfl_xor_sync(0xffffffffu, p, 2, 16);
        p += __shfl_xor_sync(0xffffffffu, p, 1, 16);
        if (n == 0)
            g_y[mi] = rtf32((p + uu * Dd) * siluf(vv));
        mi += D_INNER; xi += XDBL_W;
        dlt = ndlt; uu = nuu; Bn = nBn; Cn = nCn; vv = nvv;
    }
}

// ---------------- launch ----------------
extern "C" void kernel_launch(void* const* d_in, const int* in_sizes, int n_in,
                              void* d_out, int out_size)
{
    const float* x      = (const float*)d_in[0];
    const float* ln_g   = (const float*)d_in[1];
    const float* ln_b   = (const float*)d_in[2];
    const float* W_in   = (const float*)d_in[3];
    const float* conv_w = (const float*)d_in[4];
    const float* conv_b = (const float*)d_in[5];
    const float* W_xprj = (const float*)d_in[6];
    const float* W_dt   = (const float*)d_in[7];
    const float* b_dt   = (const float*)d_in[8];
    const float* log_A  = (const float*)d_in[9];
    const float* D_par  = (const float*)d_in[10];
    const float* W_out  = (const float*)d_in[11];
    float* out = (float*)d_out;

    float *p_xn, *p_u, *p_v, *p_uc, *p_xdbl, *p_delta, *p_y, *p_wc;
    cudaGetSymbolAddress((void**)&p_xn,    g_xn);
    cudaGetSymbolAddress((void**)&p_u,     g_u);
    cudaGetSymbolAddress((void**)&p_v,     g_v);
    cudaGetSymbolAddress((void**)&p_uc,    g_uc);
    cudaGetSymbolAddress((void**)&p_xdbl,  g_xdbl);
    cudaGetSymbolAddress((void**)&p_delta, g_delta);
    cudaGetSymbolAddress((void**)&p_y,     g_y);
    cudaGetSymbolAddress((void**)&p_wc,    g_wc);

    // smem per stage: (BM*36 + 32*(BN+8)) * 4 bytes, 3 stages
    auto smem3 = [](int BM, int BN) {
        return (size_t)3 * (BM * 36 + 32 * (BN + 8)) * 4;
    };
    const size_t sm_128_128 = smem3(128, 128);   // 107520
    const size_t sm_64_32   = smem3(64, 32);     // 43008

    cudaFuncSetAttribute((const void*)tf32_gemm<128, 128, 1>,
                         cudaFuncAttributeMaxDynamicSharedMemorySize, (int)sm_128_128);
    cudaFuncSetAttribute((const void*)tf32_gemm<128, 128, 2>,
                         cudaFuncAttributeMaxDynamicSharedMemorySize, (int)sm_128_128);
    cudaFuncSetAttribute((const void*)tf32_gemm<128, 128, 3>,
                         cudaFuncAttributeMaxDynamicSharedMemorySize, (int)sm_128_128);
    cudaFuncSetAttribute((const void*)tf32_gemm<64, 32, 0>,
                         cudaFuncAttributeMaxDynamicSharedMemorySize, (int)sm_64_32);

    // 0. weight conversion to tf32 (rna)
    {
        const int T4 = (WIN_SZ + WXP_SZ + WDT_SZ + WOUT_SZ) / 4;
        cvt_weights_kernel<<<(T4 + 255) / 256, 256>>>(W_in, W_xprj, W_dt, W_out);
    }

    // 1. LayerNorm (tf32-rounded out)
    ln_kernel<<<MTOT, 256>>>(x, ln_g, ln_b);

    // 2. GEMM1: uv = xn @ W_in  (4096 x 3072 x 768), split u/v
    tf32_gemm<128, 128, 1><<<dim3(2 * D_INNER / 128, MTOT / 128), 256, sm_128_128>>>(
        p_xn, D_MODEL, p_wc, 2 * D_INNER, p_u, D_INNER, D_MODEL, nullptr, p_v);

    // 3. depthwise causal conv + silu (tf32-rounded out)
    conv_silu_kernel<<<(MTOT * (D_INNER / 4) + 255) / 256, 256>>>(conv_w, conv_b);

    // 4. GEMM2: x_dbl = uc @ W_xproj  (4096 x 128 x 1536), tf32-rounded out
    tf32_gemm<64, 32, 0><<<dim3(XDBL_W / 32, MTOT / 64), 256, sm_64_32>>>(
        p_uc, D_INNER, p_wc + WXP_OFF, XDBL_W, p_xdbl, XDBL_W, D_INNER,
        nullptr, nullptr);

    // 5. GEMM3: delta = softplus(x_dbl[:, :96] @ W_dt + b_dt)  (4096 x 1536 x 96)
    tf32_gemm<128, 128, 2><<<dim3(D_INNER / 128, MTOT / 128), 256, sm_128_128>>>(
        p_xdbl, XDBL_W, p_wc + WDT_OFF, D_INNER, p_delta, D_INNER, DT_RANK,
        b_dt, nullptr);

    // 6. fused selective scan + skip + gate (tf32-rounded y)
    scan_kernel<<<dim3(D_INNER / 8, BATCH), 128>>>(log_A, D_par);

    // 7. GEMM_out: out = y_gated @ W_out + x  (4096 x 768 x 1536)
    tf32_gemm<128, 128, 3><<<dim3(D_MODEL / 128, MTOT / 128), 256, sm_128_128>>>(
        p_y, D_INNER, p_wc + WOUT_OFF, D_MODEL, out, D_MODEL, D_INNER, x, nullptr);
}

// round 13
// speedup vs baseline: 2.6957x; 1.1286x over previous
#include <cuda_runtime.h>
#include <cuda_fp16.h>
#include <math.h>
#include <stdint.h>

#define D_MODEL 768
#define D_INNER 1536
#define D_STATE 16
#define DT_RANK 96
#define SEQ     2048
#define BATCH   2
#define MTOT    (BATCH * SEQ)   // 4096
#define XDBL_W  128             // DT_RANK + 2*D_STATE

// ---------------- scratch (device globals: allocation-free) ----------------
__device__ float g_u    [MTOT * D_INNER];
__device__ float g_v    [MTOT * D_INNER];
__device__ float g_xdbl [MTOT * XDBL_W];
__device__ float g_delta[MTOT * D_INNER];

__device__ __align__(16) __half g_xnh[MTOT * D_MODEL];   // LN out (GEMM1 A)
__device__ __align__(16) __half g_uch[MTOT * D_INNER];   // conv+silu out (GEMM2 A, scan u)
__device__ __align__(16) __half g_xdh[MTOT * XDBL_W];    // xdbl half (GEMM3 A)
__device__ __align__(16) __half g_yh [MTOT * D_INNER];   // scan out (GEMM_out A)

// transposed half weights Wt[n][k] = W[k][n]
__device__ __align__(16) __half g_wint [2 * D_INNER * D_MODEL];  // [3072][768]
__device__ __align__(16) __half g_wxpt [XDBL_W * D_INNER];       // [128][1536]
__device__ __align__(16) __half g_wdtt [D_INNER * DT_RANK];      // [1536][96]
__device__ __align__(16) __half g_woutt[D_MODEL * D_INNER];      // [768][1536]

__device__ __forceinline__ float siluf(float x) {
    return x / (1.f + __expf(-x));
}
__device__ __forceinline__ void cp_async16(unsigned saddr, const void* gptr) {
    asm volatile("cp.async.cg.shared.global [%0], [%1], 16;"
                 :: "r"(saddr), "l"(gptr));
}

// ---------------- weight transpose fp32[K0][N] -> half[N][K0] ----------------
__global__ __launch_bounds__(256) void cvt_w_kernel(
    const float* __restrict__ src, __half* __restrict__ dst, int K0, int N)
{
    int idx = blockIdx.x * 256 + threadIdx.x;
    if (idx >= N * K0) return;
    int k = idx % K0;
    int n = idx / K0;
    dst[idx] = __float2half_rn(src[(size_t)k * N + n]);
}

// ---------------- LayerNorm -> half ----------------
__global__ __launch_bounds__(256) void ln_kernel(
    const float* __restrict__ x, const float* __restrict__ g,
    const float* __restrict__ b)
{
    int row = blockIdx.x;
    int tid = threadIdx.x;
    const float* xr = x + (size_t)row * D_MODEL;
    float v0 = xr[tid], v1 = xr[tid + 256], v2 = xr[tid + 512];
    float s  = v0 + v1 + v2;
    float sq = v0 * v0 + v1 * v1 + v2 * v2;
    #pragma unroll
    for (int o = 16; o > 0; o >>= 1) {
        s  += __shfl_xor_sync(0xffffffffu, s,  o);
        sq += __shfl_xor_sync(0xffffffffu, sq, o);
    }
    __shared__ float ss[8], ssq[8];
    __shared__ float s_mu, s_rstd;
    if ((tid & 31) == 0) { ss[tid >> 5] = s; ssq[tid >> 5] = sq; }
    __syncthreads();
    if (tid == 0) {
        float ts = 0.f, tq = 0.f;
        #pragma unroll
        for (int i = 0; i < 8; i++) { ts += ss[i]; tq += ssq[i]; }
        float mu  = ts / D_MODEL;
        float var = tq / D_MODEL - mu * mu;
        s_mu = mu; s_rstd = rsqrtf(var + 1e-5f);
    }
    __syncthreads();
    float mu = s_mu, rstd = s_rstd;
    size_t base = (size_t)row * D_MODEL;
    g_xnh[base + tid      ] = __float2half_rn((v0 - mu) * rstd * g[tid      ] + b[tid      ]);
    g_xnh[base + tid + 256] = __float2half_rn((v1 - mu) * rstd * g[tid + 256] + b[tid + 256]);
    g_xnh[base + tid + 512] = __float2half_rn((v2 - mu) * rstd * g[tid + 512] + b[tid + 512]);
}

// ---------------- fp16 m16n8k16 GEMM, 4-stage cp.async pipeline ----------------
// C[M,N] = A[M,K] @ Bt[N,K]^T, fp16 inputs, fp32 accumulate.
// 256 threads = 8 warps (4 M x 2 N). BK=32.
// EPI 0: C fp32 + Ch half (xdbl)       EPI 1: split u/v fp32
// EPI 2: softplus(acc + extra[gn])     EPI 3: acc + extra[gm*ldc+gn]
template<int BM, int BN, int EPI>
__global__ __launch_bounds__(256, 2) void h_gemm(
    const __half* __restrict__ A, int lda,
    const __half* __restrict__ Bg, int ldb,
    int K, float* __restrict__ C, int ldc,
    const float* __restrict__ extra, float* __restrict__ C2,
    __half* __restrict__ Ch)
{
    constexpr int BK = 32;
    constexpr int STAGES = 4;
    constexpr int ASTR = BK + 8;              // 40 halfs = 80B rows: banks (20g+t4)%32 distinct
    constexpr int ATILE = BM * ASTR;          // halfs
    constexpr int BTILE = BN * ASTR;
    constexpr int STAGE_H = ATILE + BTILE;
    constexpr int WM = BM / 4, WN = BN / 2;
    constexpr int MT = WM / 16, NT = WN / 8;
    constexpr int ACH = BM * 4;               // 16B chunks per A tile
    constexpr int BCH = BN * 4;

    extern __shared__ __half sh[];
    unsigned sbase;
    {
        uint64_t tmp = __cvta_generic_to_shared(sh);
        sbase = (unsigned)tmp;
    }

    const int tid   = threadIdx.x;
    const int lane  = tid & 31;
    const int wid   = tid >> 5;
    const int warpM = wid & 3;
    const int warpN = wid >> 2;
    const int g  = lane >> 2;
    const int t4 = lane & 3;
    const int m0 = blockIdx.y * BM;
    const int n0 = blockIdx.x * BN;
    const int wm0 = warpM * WM;
    const int wn0 = warpN * WN;
    const int KT = K / BK;

    auto fill = [&](int s) {
        if (s < KT) {
            int k0 = s * BK;
            unsigned ab = sbase + (unsigned)((s % STAGES) * STAGE_H) * 2u;
            unsigned bb = ab + (unsigned)ATILE * 2u;
            #pragma unroll
            for (int c = tid; c < ACH; c += 256) {
                int r = c >> 2, q = c & 3;
                cp_async16(ab + (unsigned)(r * ASTR + q * 8) * 2u,
                           &A[(size_t)(m0 + r) * lda + k0 + q * 8]);
            }
            #pragma unroll
            for (int c = tid; c < BCH; c += 256) {
                int r = c >> 2, q = c & 3;
                cp_async16(bb + (unsigned)(r * ASTR + q * 8) * 2u,
                           &Bg[(size_t)(n0 + r) * ldb + k0 + q * 8]);
            }
        }
        asm volatile("cp.async.commit_group;");
    };

    float acc[MT][NT][4];
    #pragma unroll
    for (int i = 0; i < MT; i++)
        #pragma unroll
        for (int j = 0; j < NT; j++)
            #pragma unroll
            for (int c = 0; c < 4; c++) acc[i][j][c] = 0.f;

    fill(0); fill(1); fill(2);

    for (int it = 0; it < KT; it++) {
        asm volatile("cp.async.wait_group 2;");
        __syncthreads();
        fill(it + 3);   // writes stage (it+3)%4 == (it-1)%4, consumed last iter

        const __half* As = sh + (it % STAGES) * STAGE_H;
        const __half* Bs = As + ATILE;

        #pragma unroll
        for (int kk = 0; kk < BK; kk += 16) {
            uint32_t a[MT][4], b[NT][2];
            #pragma unroll
            for (int mt = 0; mt < MT; mt++) {
                const __half* ap = As + (wm0 + mt * 16 + g) * ASTR + kk + 2 * t4;
                a[mt][0] = *(const uint32_t*)ap;
                a[mt][1] = *(const uint32_t*)(ap + 8 * ASTR);
                a[mt][2] = *(const uint32_t*)(ap + 8);
                a[mt][3] = *(const uint32_t*)(ap + 8 * ASTR + 8);
            }
            #pragma unroll
            for (int nt = 0; nt < NT; nt++) {
                const __half* bp = Bs + (wn0 + nt * 8 + g) * ASTR + kk + 2 * t4;
                b[nt][0] = *(const uint32_t*)bp;
                b[nt][1] = *(const uint32_t*)(bp + 8);
            }
            #pragma unroll
            for (int mt = 0; mt < MT; mt++)
                #pragma unroll
                for (int nt = 0; nt < NT; nt++) {
                    asm volatile(
                        "mma.sync.aligned.m16n8k16.row.col.f32.f16.f16.f32 "
                        "{%0,%1,%2,%3},{%4,%5,%6,%7},{%8,%9},{%0,%1,%2,%3};\n"
                        : "+f"(acc[mt][nt][0]), "+f"(acc[mt][nt][1]),
                          "+f"(acc[mt][nt][2]), "+f"(acc[mt][nt][3])
                        : "r"(a[mt][0]), "r"(a[mt][1]),
                          "r"(a[mt][2]), "r"(a[mt][3]),
                          "r"(b[nt][0]), "r"(b[nt][1]));
                }
        }
    }

    // ---------------- epilogue ----------------
    #pragma unroll
    for (int mt = 0; mt < MT; mt++) {
        #pragma unroll
        for (int nt = 0; nt < NT; nt++) {
            int gm = m0 + wm0 + mt * 16 + g;
            int gn = n0 + wn0 + nt * 8 + 2 * t4;
            #pragma unroll
            for (int half_ = 0; half_ < 2; half_++) {
                int row = gm + half_ * 8;
                float v0 = acc[mt][nt][half_ * 2];
                float v1 = acc[mt][nt][half_ * 2 + 1];
                if (EPI == 0) {
                    *(float2*)&C[(size_t)row * ldc + gn] = make_float2(v0, v1);
                    __half2 hv;
                    hv.x = __float2half_rn(v0);
                    hv.y = __float2half_rn(v1);
                    *(__half2*)&Ch[(size_t)row * ldc + gn] = hv;
                } else if (EPI == 1) {
                    if (gn < D_INNER)
                        *(float2*)&C [(size_t)row * D_INNER + gn] = make_float2(v0, v1);
                    else
                        *(float2*)&C2[(size_t)row * D_INNER + gn - D_INNER] = make_float2(v0, v1);
                } else if (EPI == 2) {
                    float t0 = v0 + extra[gn];
                    float t1 = v1 + extra[gn + 1];
                    t0 = (t0 > 20.f) ? t0 : log1pf(__expf(t0));
                    t1 = (t1 > 20.f) ? t1 : log1pf(__expf(t1));
                    *(float2*)&C[(size_t)row * ldc + gn] = make_float2(t0, t1);
                } else {
                    float2 r = *(const float2*)&extra[(size_t)row * ldc + gn];
                    *(float2*)&C[(size_t)row * ldc + gn] =
                        make_float2(v0 + r.x, v1 + r.y);
                }
            }
        }
    }
}

// ---------------- causal depthwise conv (k=4) + bias + silu -> half ----------------
__global__ __launch_bounds__(256) void conv_silu_kernel(
    const float* __restrict__ cw, const float* __restrict__ cb)
{
    int idx = blockIdx.x * 256 + threadIdx.x;
    if (idx >= MTOT * (D_INNER / 4)) return;
    int d4 = idx % (D_INNER / 4);
    int m  = idx / (D_INNER / 4);
    int d  = d4 * 4;
    int l  = m & (SEQ - 1);

    float4 w0 = *(const float4*)&cw[(d    ) * 4];
    float4 w1 = *(const float4*)&cw[(d + 1) * 4];
    float4 w2 = *(const float4*)&cw[(d + 2) * 4];
    float4 w3 = *(const float4*)&cw[(d + 3) * 4];
    float wt[4][4] = {{w0.x,w0.y,w0.z,w0.w},{w1.x,w1.y,w1.z,w1.w},
                      {w2.x,w2.y,w2.z,w2.w},{w3.x,w3.y,w3.z,w3.w}};

    float4 a = *(const float4*)&cb[d];
    #pragma unroll
    for (int j = 0; j < 4; j++) {
        int li = l + j - 3;
        if (li >= 0) {
            float4 uv = *(const float4*)&g_u[(size_t)(m + j - 3) * D_INNER + d];
            a.x = fmaf(wt[0][j], uv.x, a.x);
            a.y = fmaf(wt[1][j], uv.y, a.y);
            a.z = fmaf(wt[2][j], uv.z, a.z);
            a.w = fmaf(wt[3][j], uv.w, a.w);
        }
    }
    __half h4[4];
    h4[0] = __float2half_rn(siluf(a.x));
    h4[1] = __float2half_rn(siluf(a.y));
    h4[2] = __float2half_rn(siluf(a.z));
    h4[3] = __float2half_rn(siluf(a.w));
    *(uint2*)&g_uch[(size_t)m * D_INNER + d] = *(uint2*)h4;
}

// ---------------- selective scan (fused + gate) -> half y ----------------
// 128 threads = 8 d-channels x 16 states. grid (D_INNER/8, BATCH).
__global__ __launch_bounds__(128) void scan_kernel(
    const float* __restrict__ logA, const float* __restrict__ Dp)
{
    int tid = threadIdx.x;
    int n  = tid & 15;
    int dl = tid >> 4;
    int d  = blockIdx.x * 8 + dl;
    int b  = blockIdx.y;

    float Adn = -expf(logA[d * D_STATE + n]);
    float Dd  = Dp[d];
    float h   = 0.f;

    size_t mi = (size_t)(b * SEQ) * D_INNER + d;
    size_t xi = (size_t)(b * SEQ) * XDBL_W + DT_RANK + n;

    float dlt = g_delta[mi];
    float uu  = __half2float(g_uch[mi]);
    float Bn  = g_xdbl[xi];
    float Cn  = g_xdbl[xi + D_STATE];
    float vv  = g_v[mi];

    for (int l = 0; l < SEQ; l++) {
        float ndlt = 0.f, nuu = 0.f, nBn = 0.f, nCn = 0.f, nvv = 0.f;
        if (l + 1 < SEQ) {
            size_t mi2 = mi + D_INNER, xi2 = xi + XDBL_W;
            ndlt = g_delta[mi2];
            nuu  = __half2float(g_uch[mi2]);
            nBn  = g_xdbl[xi2];
            nCn  = g_xdbl[xi2 + D_STATE];
            nvv  = g_v[mi2];
        }
        float e = __expf(dlt * Adn);
        h = fmaf(e, h, dlt * Bn * uu);
        float p = h * Cn;
        p += __shfl_xor_sync(0xffffffffu, p, 8, 16);
        p += __shfl_xor_sync(0xffffffffu, p, 4, 16);
        p += __shfl_xor_sync(0xffffffffu, p, 2, 16);
        p += __shfl_xor_sync(0xffffffffu, p, 1, 16);
        if (n == 0) {
            float y = (p + uu * Dd) * siluf(vv);
            g_yh[mi] = __float2half_rn(y);
        }
        mi += D_INNER; xi += XDBL_W;
        dlt = ndlt; uu = nuu; Bn = nBn; Cn = nCn; vv = nvv;
    }
}

// ---------------- launch ----------------
extern "C" void kernel_launch(void* const* d_in, const int* in_sizes, int n_in,
                              void* d_out, int out_size)
{
    const float* x      = (const float*)d_in[0];
    const float* ln_g   = (const float*)d_in[1];
    const float* ln_b   = (const float*)d_in[2];
    const float* W_in   = (const float*)d_in[3];
    const float* conv_w = (const float*)d_in[4];
    const float* conv_b = (const float*)d_in[5];
    const float* W_xprj = (const float*)d_in[6];
    const float* W_dt   = (const float*)d_in[7];
    const float* b_dt   = (const float*)d_in[8];
    const float* log_A  = (const float*)d_in[9];
    const float* D_par  = (const float*)d_in[10];
    const float* W_out  = (const float*)d_in[11];
    float* out = (float*)d_out;

    float *p_u, *p_v, *p_xdbl, *p_delta;
    cudaGetSymbolAddress((void**)&p_u,     g_u);
    cudaGetSymbolAddress((void**)&p_v,     g_v);
    cudaGetSymbolAddress((void**)&p_xdbl,  g_xdbl);
    cudaGetSymbolAddress((void**)&p_delta, g_delta);

    __half *p_xnh, *p_uch, *p_xdh, *p_yh;
    __half *p_wint, *p_wxpt, *p_wdtt, *p_woutt;
    cudaGetSymbolAddress((void**)&p_xnh,   g_xnh);
    cudaGetSymbolAddress((void**)&p_uch,   g_uch);
    cudaGetSymbolAddress((void**)&p_xdh,   g_xdh);
    cudaGetSymbolAddress((void**)&p_yh,    g_yh);
    cudaGetSymbolAddress((void**)&p_wint,  g_wint);
    cudaGetSymbolAddress((void**)&p_wxpt,  g_wxpt);
    cudaGetSymbolAddress((void**)&p_wdtt,  g_wdtt);
    cudaGetSymbolAddress((void**)&p_woutt, g_woutt);

    // dynamic smem: STAGES(4) * (BM+BN) * 40 halfs * 2B
    const int sm_128_128 = 4 * (128 + 128) * 40 * 2;   // 81920
    const int sm_64_32   = 4 * (64 + 32) * 40 * 2;     // 30720

    cudaFuncSetAttribute((const void*)h_gemm<128, 128, 1>,
        cudaFuncAttributeMaxDynamicSharedMemorySize, sm_128_128);
    cudaFuncSetAttribute((const void*)h_gemm<128, 128, 2>,
        cudaFuncAttributeMaxDynamicSharedMemorySize, sm_128_128);
    cudaFuncSetAttribute((const void*)h_gemm<128, 128, 3>,
        cudaFuncAttributeMaxDynamicSharedMemorySize, sm_128_128);
    cudaFuncSetAttribute((const void*)h_gemm<64, 32, 0>,
        cudaFuncAttributeMaxDynamicSharedMemorySize, sm_64_32);

    // 0. weight transpose to half
    cvt_w_kernel<<<(2 * D_INNER * D_MODEL + 255) / 256, 256>>>(
        W_in, p_wint, D_MODEL, 2 * D_INNER);
    cvt_w_kernel<<<(XDBL_W * D_INNER + 255) / 256, 256>>>(
        W_xprj, p_wxpt, D_INNER, XDBL_W);
    cvt_w_kernel<<<(D_INNER * DT_RANK + 255) / 256, 256>>>(
        W_dt, p_wdtt, DT_RANK, D_INNER);
    cvt_w_kernel<<<(D_MODEL * D_INNER + 255) / 256, 256>>>(
        W_out, p_woutt, D_INNER, D_MODEL);

    // 1. LayerNorm
    ln_kernel<<<MTOT, 256>>>(x, ln_g, ln_b);

    // 2. GEMM1: uv = xn @ W_in (M=4096, N=3072, K=768), split u/v
    h_gemm<128, 128, 1><<<dim3(2 * D_INNER / 128, MTOT / 128), 256, sm_128_128>>>(
        p_xnh, D_MODEL, p_wint, D_MODEL, D_MODEL,
        p_u, D_INNER, nullptr, p_v, nullptr);

    // 3. depthwise causal conv + silu
    conv_silu_kernel<<<(MTOT * (D_INNER / 4) + 255) / 256, 256>>>(conv_w, conv_b);

    // 4. GEMM2: x_dbl = uc @ W_xproj (M=4096, N=128, K=1536), fp32 + half out
    h_gemm<64, 32, 0><<<dim3(XDBL_W / 32, MTOT / 64), 256, sm_64_32>>>(
        p_uch, D_INNER, p_wxpt, D_INNER, D_INNER,
        p_xdbl, XDBL_W, nullptr, nullptr, p_xdh);

    // 5. GEMM3: delta = softplus(x_dbl[:, :96] @ W_dt + b_dt) (M=4096, N=1536, K=96)
    h_gemm<128, 128, 2><<<dim3(D_INNER / 128, MTOT / 128), 256, sm_128_128>>>(
        p_xdh, XDBL_W, p_wdtt, DT_RANK, DT_RANK,
        p_delta, D_INNER, b_dt, nullptr, nullptr);

    // 6. fused selective scan + skip + gate
    scan_kernel<<<dim3(D_INNER / 8, BATCH), 128>>>(log_A, D_par);

    // 7. GEMM_out: out = y @ W_out + x (M=4096, N=768, K=1536)
    h_gemm<128, 128, 3><<<dim3(D_MODEL / 128, MTOT / 128), 256, sm_128_128>>>(
        p_yh, D_INNER, p_woutt, D_INNER, D_INNER,
        out, D_MODEL, x, nullptr, nullptr);
}